// round 9
// baseline (speedup 1.0000x reference)
#include <cuda_runtime.h>
#include <cuda_bf16.h>
#include <math.h>

#define D 256
#define K 5
#define THREADS 256
#define MIN_BLOCKS_PER_SM 5
#define BLOCKS 740                     // 148 SMs * 5 resident blocks = exactly one wave
#define WARPS_PER_BLOCK (THREADS / 32)
#define TOTAL_WARPS (BLOCKS * WARPS_PER_BLOCK)
#define RED_THREADS 1024
#define NCAND (BLOCKS * K)             // 3700
#define PER_T ((NCAND + RED_THREADS - 1) / RED_THREADS)   // 4

// Scratch (static device globals -- no allocation allowed)
__device__ float2 g_cand[NCAND];       // {val, idx as float bits}

// tie-break matches jax top_k: higher value first; equal value -> lower index first
__device__ __forceinline__ bool better(float v, int i, float V, int I) {
    return (v > V) || (v == V && i < I);
}

__device__ __forceinline__ void insert_top5(float v, int i, float tv[K], int ti[K]) {
    if (!better(v, i, tv[K - 1], ti[K - 1])) return;
    tv[K - 1] = v; ti[K - 1] = i;
#pragma unroll
    for (int j = K - 1; j > 0; --j) {
        if (better(tv[j], ti[j], tv[j - 1], ti[j - 1])) {
            float fv = tv[j]; tv[j] = tv[j - 1]; tv[j - 1] = fv;
            int   fi = ti[j]; ti[j] = ti[j - 1]; ti[j - 1] = fi;
        }
    }
}

// merge partner lane's sorted 5-list into mine via shuffles (butterfly step)
__device__ __forceinline__ void shfl_merge5(float tv[K], int ti[K], int xorMask) {
    float pv[K]; int pi[K];
#pragma unroll
    for (int j = 0; j < K; ++j) {
        pv[j] = __shfl_xor_sync(0xffffffffu, tv[j], xorMask);
        pi[j] = __shfl_xor_sync(0xffffffffu, ti[j], xorMask);
    }
#pragma unroll
    for (int j = 0; j < K; ++j)
        insert_top5(pv[j], pi[j], tv, ti);
}

// -------- Kernel 1: scan (query norm fused, per-block top-5) --------
__global__ void __launch_bounds__(THREADS, MIN_BLOCKS_PER_SM)
knn_scan(const float* __restrict__ q, const float* __restrict__ emb, int n) {
    __shared__ float s_q[D];
    __shared__ float s_part[WARPS_PER_BLOCK];
    __shared__ float s_norm;
    __shared__ float mv[THREADS * K];
    __shared__ int   mi[THREADS * K];

    const int t    = threadIdx.x;
    const int lane = t & 31;

    // --- normalize query into smem (per block; L2-resident after first block) ---
    {
        float v = q[t];
        float sq = v * v;
#pragma unroll
        for (int off = 16; off > 0; off >>= 1)
            sq += __shfl_down_sync(0xffffffffu, sq, off);
        if (lane == 0) s_part[t >> 5] = sq;
        __syncthreads();
        if (t == 0) {
            float tot = 0.f;
#pragma unroll
            for (int i = 0; i < WARPS_PER_BLOCK; ++i) tot += s_part[i];
            s_norm = fmaxf(sqrtf(tot), 1e-12f);
        }
        __syncthreads();
        s_q[t] = v / s_norm;
        __syncthreads();
    }

    const float4* sq4 = (const float4*)s_q;
    const float4 q0 = sq4[lane];
    const float4 q1 = sq4[lane + 32];

    float tv[K]; int ti[K];
#pragma unroll
    for (int j = 0; j < K; ++j) { tv[j] = -INFINITY; ti[j] = 0x7fffffff; }

    const int warp = (blockIdx.x * THREADS + t) >> 5;
    const int chunk = (n + TOTAL_WARPS - 1) / TOTAL_WARPS;
    int rbeg = warp * chunk;
    int rend = rbeg + chunk; if (rend > n) rend = n;
    if (rbeg > n) rbeg = n;

    const bool h16 = (lane & 16) != 0;
    const bool h8  = (lane & 8)  != 0;
    const int r_off = (h16 ? 1 : 0) + (h8 ? 2 : 0);
    const bool do_ins = (lane & 7) == 0;

    int row = rbeg;
    for (; row + 4 <= rend; row += 4) {
        float4 A[4], B[4];
#pragma unroll
        for (int r = 0; r < 4; ++r) {
            const float4* e = (const float4*)(emb + (size_t)(row + r) * D);
            A[r] = e[lane];
            B[r] = e[lane + 32];
        }
        float d[4];
#pragma unroll
        for (int r = 0; r < 4; ++r) {
            float s = fmaf(A[r].x, q0.x, fmaf(A[r].y, q0.y, fmaf(A[r].z, q0.z, A[r].w * q0.w)));
            d[r] = fmaf(B[r].x, q1.x, fmaf(B[r].y, q1.y, fmaf(B[r].z, q1.z, fmaf(B[r].w, q1.w, s))));
        }
        // 4-way warp reduce in 5 shuffles:
        float send01 = h16 ? d[0] : d[1];
        float s01 = (h16 ? d[1] : d[0]) + __shfl_xor_sync(0xffffffffu, send01, 16);
        float send23 = h16 ? d[2] : d[3];
        float s23 = (h16 ? d[3] : d[2]) + __shfl_xor_sync(0xffffffffu, send23, 16);
        float send = h8 ? s01 : s23;
        float s = (h8 ? s23 : s01) + __shfl_xor_sync(0xffffffffu, send, 8);
        s += __shfl_xor_sync(0xffffffffu, s, 4);
        s += __shfl_xor_sync(0xffffffffu, s, 2);
        s += __shfl_xor_sync(0xffffffffu, s, 1);
        // lanes 0,8,16,24 hold totals of rows row+0, row+2, row+1, row+3
        if (do_ins) insert_top5(s, row + r_off, tv, ti);
    }
    // remainder rows (<=3)
    for (; row < rend; ++row) {
        const float4* e = (const float4*)(emb + (size_t)row * D);
        float4 a = e[lane], b = e[lane + 32];
        float s = fmaf(a.x, q0.x, fmaf(a.y, q0.y, fmaf(a.z, q0.z, a.w * q0.w)));
        s = fmaf(b.x, q1.x, fmaf(b.y, q1.y, fmaf(b.z, q1.z, fmaf(b.w, q1.w, s))));
#pragma unroll
        for (int off = 16; off > 0; off >>= 1)
            s += __shfl_xor_sync(0xffffffffu, s, off);
        if (lane == 0) insert_top5(s, row, tv, ti);
    }

    // --- per-block merge of 256 per-thread lists -> block top-5 ---
#pragma unroll
    for (int j = 0; j < K; ++j) { mv[t * K + j] = tv[j]; mi[t * K + j] = ti[j]; }
    for (int sft = THREADS / 2; sft >= 1; sft >>= 1) {
        __syncthreads();
        if (t < sft) {
#pragma unroll
            for (int j = 0; j < K; ++j) { tv[j] = mv[t * K + j]; ti[j] = mi[t * K + j]; }
#pragma unroll
            for (int j = 0; j < K; ++j)
                insert_top5(mv[(t + sft) * K + j], mi[(t + sft) * K + j], tv, ti);
#pragma unroll
            for (int j = 0; j < K; ++j) { mv[t * K + j] = tv[j]; mi[t * K + j] = ti[j]; }
        }
    }
    __syncthreads();
    if (t == 0) {
#pragma unroll
        for (int j = 0; j < K; ++j)
            g_cand[blockIdx.x * K + j] = make_float2(mv[j], __int_as_float(mi[j]));
    }
}

// -------- Kernel 2: latency-optimized reduce (float2 loads, shuffle butterflies) --------
__global__ void __launch_bounds__(RED_THREADS) knn_reduce(float* __restrict__ out) {
    __shared__ float2 s_list[(RED_THREADS / 32) * K];   // 32 warp lists
    const int t    = threadIdx.x;
    const int lane = t & 31;
    const int wid  = t >> 5;

    // Phase 1: batched independent float2 loads (max MLP, single latency wall)
    float cv[PER_T]; int ci[PER_T];
#pragma unroll
    for (int u = 0; u < PER_T; ++u) {
        int c = t + u * RED_THREADS;
        if (c < NCAND) {
            float2 p = g_cand[c];
            cv[u] = p.x; ci[u] = __float_as_int(p.y);
        } else {
            cv[u] = -INFINITY; ci[u] = 0x7fffffff;
        }
    }

    // Phase 2: local top-5, then intra-warp butterfly merge (no barriers)
    float tv[K]; int ti[K];
#pragma unroll
    for (int j = 0; j < K; ++j) { tv[j] = -INFINITY; ti[j] = 0x7fffffff; }
#pragma unroll
    for (int u = 0; u < PER_T; ++u)
        insert_top5(cv[u], ci[u], tv, ti);

    shfl_merge5(tv, ti, 16);
    shfl_merge5(tv, ti, 8);
    shfl_merge5(tv, ti, 4);
    shfl_merge5(tv, ti, 2);
    shfl_merge5(tv, ti, 1);

    // Phase 3: one warp list per warp -> smem, warp 0 butterflies the 32 lists
    if (lane < K) s_list[wid * K + lane] = make_float2(tv[lane], __int_as_float(ti[lane]));
    __syncthreads();

    if (wid == 0) {
#pragma unroll
        for (int j = 0; j < K; ++j) {
            float2 p = s_list[lane * K + j];
            tv[j] = p.x; ti[j] = __float_as_int(p.y);
        }
        shfl_merge5(tv, ti, 16);
        shfl_merge5(tv, ti, 8);
        shfl_merge5(tv, ti, 4);
        shfl_merge5(tv, ti, 2);
        shfl_merge5(tv, ti, 1);
        if (lane == 0) {
#pragma unroll
            for (int j = 0; j < K; ++j) {
                out[j]     = (float)ti[j];   // top_idx (reference tuple order: idx first)
                out[K + j] = tv[j];          // top_vals
            }
        }
    }
}

extern "C" void kernel_launch(void* const* d_in, const int* in_sizes, int n_in,
                              void* d_out, int out_size) {
    const float* q   = (const float*)d_in[0];   // [1, 256]
    const float* emb = (const float*)d_in[1];   // [N, 256]
    const int n = in_sizes[1] / D;

    knn_scan<<<BLOCKS, THREADS>>>(q, emb, n);
    knn_reduce<<<1, RED_THREADS>>>((float*)d_out);
}

// round 10
// speedup vs baseline: 1.0243x; 1.0243x over previous
#include <cuda_runtime.h>
#include <cuda_bf16.h>
#include <math.h>

#define D 256
#define K 5
#define THREADS 256
#define MIN_BLOCKS_PER_SM 5
#define BLOCKS 740                     // 148 SMs * 5 resident blocks = exactly one wave
#define WARPS_PER_BLOCK (THREADS / 32)
#define TOTAL_WARPS (BLOCKS * WARPS_PER_BLOCK)
#define RED_THREADS 256
#define NCAND (BLOCKS * K)             // 3700
#define PER_T ((NCAND + RED_THREADS - 1) / RED_THREADS)   // 15
#define STEAL_TILE 16                  // rows per stolen tile

// Scratch (static device globals -- no allocation allowed)
__device__ float2 g_cand[NCAND];       // {val, idx as float bits}
__device__ unsigned int g_work = 0;

// tie-break matches jax top_k: higher value first; equal value -> lower index first
__device__ __forceinline__ bool better(float v, int i, float V, int I) {
    return (v > V) || (v == V && i < I);
}

__device__ __forceinline__ void insert_top5(float v, int i, float tv[K], int ti[K]) {
    if (!better(v, i, tv[K - 1], ti[K - 1])) return;
    tv[K - 1] = v; ti[K - 1] = i;
#pragma unroll
    for (int j = K - 1; j > 0; --j) {
        if (better(tv[j], ti[j], tv[j - 1], ti[j - 1])) {
            float fv = tv[j]; tv[j] = tv[j - 1]; tv[j - 1] = fv;
            int   fi = ti[j]; ti[j] = ti[j - 1]; ti[j - 1] = fi;
        }
    }
}

// -------- Kernel 1: scan (query norm fused, hybrid static+steal, per-block top-5) ----
__global__ void __launch_bounds__(THREADS, MIN_BLOCKS_PER_SM)
knn_scan(const float* __restrict__ q, const float* __restrict__ emb, int n) {
    __shared__ float s_q[D];
    __shared__ float s_part[WARPS_PER_BLOCK];
    __shared__ float s_norm;
    __shared__ float mv[THREADS * K];
    __shared__ int   mi[THREADS * K];

    const int t    = threadIdx.x;
    const int lane = t & 31;

    // --- normalize query into smem (per block; L2-resident after first block) ---
    {
        float v = q[t];
        float sq = v * v;
#pragma unroll
        for (int off = 16; off > 0; off >>= 1)
            sq += __shfl_down_sync(0xffffffffu, sq, off);
        if (lane == 0) s_part[t >> 5] = sq;
        __syncthreads();
        if (t == 0) {
            float tot = 0.f;
#pragma unroll
            for (int i = 0; i < WARPS_PER_BLOCK; ++i) tot += s_part[i];
            s_norm = fmaxf(sqrtf(tot), 1e-12f);
        }
        __syncthreads();
        s_q[t] = v / s_norm;
        __syncthreads();
    }

    const float4* sq4 = (const float4*)s_q;
    const float4 q0 = sq4[lane];
    const float4 q1 = sq4[lane + 32];

    float tv[K]; int ti[K];
#pragma unroll
    for (int j = 0; j < K; ++j) { tv[j] = -INFINITY; ti[j] = 0x7fffffff; }

    const int warp = (blockIdx.x * THREADS + t) >> 5;
    const bool h16 = (lane & 16) != 0;
    const bool h8  = (lane & 8)  != 0;
    const int r_off = (h16 ? 1 : 0) + (h8 ? 2 : 0);
    const bool do_ins = (lane & 7) == 0;

    // static portion: 87.5% of rows, contiguous per warp, multiple of 4
    const int spw = ((n / TOTAL_WARPS) * 7 / 8) & ~3;
    const int steal_base = spw * TOTAL_WARPS;

    // ---- phase 1: static contiguous chunk (identical codegen to champion loop) ----
    {
        const int rbeg = warp * spw;
        const int rend = rbeg + spw;
        for (int row = rbeg; row < rend; row += 4) {
            float4 A[4], B[4];
#pragma unroll
            for (int r = 0; r < 4; ++r) {
                const float4* e = (const float4*)(emb + (size_t)(row + r) * D);
                A[r] = e[lane];
                B[r] = e[lane + 32];
            }
            float d[4];
#pragma unroll
            for (int r = 0; r < 4; ++r) {
                float s = fmaf(A[r].x, q0.x, fmaf(A[r].y, q0.y, fmaf(A[r].z, q0.z, A[r].w * q0.w)));
                d[r] = fmaf(B[r].x, q1.x, fmaf(B[r].y, q1.y, fmaf(B[r].z, q1.z, fmaf(B[r].w, q1.w, s))));
            }
            float send01 = h16 ? d[0] : d[1];
            float s01 = (h16 ? d[1] : d[0]) + __shfl_xor_sync(0xffffffffu, send01, 16);
            float send23 = h16 ? d[2] : d[3];
            float s23 = (h16 ? d[3] : d[2]) + __shfl_xor_sync(0xffffffffu, send23, 16);
            float send = h8 ? s01 : s23;
            float s = (h8 ? s23 : s01) + __shfl_xor_sync(0xffffffffu, send, 8);
            s += __shfl_xor_sync(0xffffffffu, s, 4);
            s += __shfl_xor_sync(0xffffffffu, s, 2);
            s += __shfl_xor_sync(0xffffffffu, s, 1);
            if (do_ins) insert_top5(s, row + r_off, tv, ti);
        }
    }

    // ---- phase 2: stolen 16-row tiles over the final 12.5% ----
    {
        unsigned int my;
        if (lane == 0) my = atomicAdd(&g_work, 1u);
        my = __shfl_sync(0xffffffffu, my, 0);

        while (steal_base + (int)(my * STEAL_TILE) < n) {
            unsigned int nxt;
            if (lane == 0) nxt = atomicAdd(&g_work, 1u);   // prefetch next tile id

            const int rbeg = steal_base + (int)(my * STEAL_TILE);
            int rend = rbeg + STEAL_TILE; if (rend > n) rend = n;

            int row = rbeg;
            for (; row + 4 <= rend; row += 4) {
                float4 A[4], B[4];
#pragma unroll
                for (int r = 0; r < 4; ++r) {
                    const float4* e = (const float4*)(emb + (size_t)(row + r) * D);
                    A[r] = e[lane];
                    B[r] = e[lane + 32];
                }
                float d[4];
#pragma unroll
                for (int r = 0; r < 4; ++r) {
                    float s = fmaf(A[r].x, q0.x, fmaf(A[r].y, q0.y, fmaf(A[r].z, q0.z, A[r].w * q0.w)));
                    d[r] = fmaf(B[r].x, q1.x, fmaf(B[r].y, q1.y, fmaf(B[r].z, q1.z, fmaf(B[r].w, q1.w, s))));
                }
                float send01 = h16 ? d[0] : d[1];
                float s01 = (h16 ? d[1] : d[0]) + __shfl_xor_sync(0xffffffffu, send01, 16);
                float send23 = h16 ? d[2] : d[3];
                float s23 = (h16 ? d[3] : d[2]) + __shfl_xor_sync(0xffffffffu, send23, 16);
                float send = h8 ? s01 : s23;
                float s = (h8 ? s23 : s01) + __shfl_xor_sync(0xffffffffu, send, 8);
                s += __shfl_xor_sync(0xffffffffu, s, 4);
                s += __shfl_xor_sync(0xffffffffu, s, 2);
                s += __shfl_xor_sync(0xffffffffu, s, 1);
                if (do_ins) insert_top5(s, row + r_off, tv, ti);
            }
            for (; row < rend; ++row) {
                const float4* e = (const float4*)(emb + (size_t)row * D);
                float4 a = e[lane], b = e[lane + 32];
                float s = fmaf(a.x, q0.x, fmaf(a.y, q0.y, fmaf(a.z, q0.z, a.w * q0.w)));
                s = fmaf(b.x, q1.x, fmaf(b.y, q1.y, fmaf(b.z, q1.z, fmaf(b.w, q1.w, s))));
#pragma unroll
                for (int off = 16; off > 0; off >>= 1)
                    s += __shfl_xor_sync(0xffffffffu, s, off);
                if (lane == 0) insert_top5(s, row, tv, ti);
            }

            my = __shfl_sync(0xffffffffu, nxt, 0);
        }
    }

    // --- per-block merge of 256 per-thread lists -> block top-5 ---
#pragma unroll
    for (int j = 0; j < K; ++j) { mv[t * K + j] = tv[j]; mi[t * K + j] = ti[j]; }
    for (int sft = THREADS / 2; sft >= 1; sft >>= 1) {
        __syncthreads();
        if (t < sft) {
#pragma unroll
            for (int j = 0; j < K; ++j) { tv[j] = mv[t * K + j]; ti[j] = mi[t * K + j]; }
#pragma unroll
            for (int j = 0; j < K; ++j)
                insert_top5(mv[(t + sft) * K + j], mi[(t + sft) * K + j], tv, ti);
#pragma unroll
            for (int j = 0; j < K; ++j) { mv[t * K + j] = tv[j]; mi[t * K + j] = ti[j]; }
        }
    }
    __syncthreads();
    if (t == 0) {
#pragma unroll
        for (int j = 0; j < K; ++j)
            g_cand[blockIdx.x * K + j] = make_float2(mv[j], __int_as_float(mi[j]));
    }
}

// -------- Kernel 2: latency-optimized reduce (R8 structure, float2 loads) --------
__global__ void __launch_bounds__(RED_THREADS) knn_reduce(float* __restrict__ out) {
    __shared__ float sv[RED_THREADS * K];
    __shared__ int   si[RED_THREADS * K];
    const int t = threadIdx.x;

    // Phase 1: batched independent float2 loads (full unroll -> max MLP)
    float cv[PER_T]; int ci[PER_T];
#pragma unroll
    for (int u = 0; u < PER_T; ++u) {
        int c = t + u * RED_THREADS;
        if (c < NCAND) {
            float2 p = g_cand[c];
            cv[u] = p.x; ci[u] = __float_as_int(p.y);
        } else {
            cv[u] = -INFINITY; ci[u] = 0x7fffffff;
        }
    }

    // Phase 2: insert into local top-5
    float tv[K]; int ti[K];
#pragma unroll
    for (int j = 0; j < K; ++j) { tv[j] = -INFINITY; ti[j] = 0x7fffffff; }
#pragma unroll
    for (int u = 0; u < PER_T; ++u)
        insert_top5(cv[u], ci[u], tv, ti);

    // Phase 3: smem tree merge (proven in R8)
#pragma unroll
    for (int j = 0; j < K; ++j) { sv[t * K + j] = tv[j]; si[t * K + j] = ti[j]; }
    for (int s = RED_THREADS / 2; s >= 1; s >>= 1) {
        __syncthreads();
        if (t < s) {
#pragma unroll
            for (int j = 0; j < K; ++j) { tv[j] = sv[t * K + j]; ti[j] = si[t * K + j]; }
#pragma unroll
            for (int j = 0; j < K; ++j)
                insert_top5(sv[(t + s) * K + j], si[(t + s) * K + j], tv, ti);
#pragma unroll
            for (int j = 0; j < K; ++j) { sv[t * K + j] = tv[j]; si[t * K + j] = ti[j]; }
        }
    }
    __syncthreads();
    if (t == 0) {
#pragma unroll
        for (int j = 0; j < K; ++j) {
            out[j]     = (float)si[j];   // top_idx (reference tuple order: idx first)
            out[K + j] = sv[j];          // top_vals
        }
        g_work = 0;                      // reset steal counter for next graph replay
    }
}

extern "C" void kernel_launch(void* const* d_in, const int* in_sizes, int n_in,
                              void* d_out, int out_size) {
    const float* q   = (const float*)d_in[0];   // [1, 256]
    const float* emb = (const float*)d_in[1];   // [N, 256]
    const int n = in_sizes[1] / D;

    knn_scan<<<BLOCKS, THREADS>>>(q, emb, n);
    knn_reduce<<<1, RED_THREADS>>>((float*)d_out);
}

// round 11
// speedup vs baseline: 1.0879x; 1.0621x over previous
#include <cuda_runtime.h>
#include <cuda_bf16.h>
#include <math.h>

#define D 256
#define K 5
#define THREADS 256
#define MIN_BLOCKS_PER_SM 5
#define BLOCKS 740                     // 148 SMs * 5 resident blocks = exactly one wave
#define WARPS_PER_BLOCK (THREADS / 32)
#define TOTAL_WARPS (BLOCKS * WARPS_PER_BLOCK)
#define RED_THREADS 512
#define NCAND (BLOCKS * K)             // 3700
#define PER_T ((NCAND + RED_THREADS - 1) / RED_THREADS)   // 8

// Scratch (static device globals -- no allocation allowed)
__device__ float g_cand_val[NCAND];
__device__ int   g_cand_idx[NCAND];

// tie-break matches jax top_k: higher value first; equal value -> lower index first
__device__ __forceinline__ bool better(float v, int i, float V, int I) {
    return (v > V) || (v == V && i < I);
}

__device__ __forceinline__ void insert_top5(float v, int i, float tv[K], int ti[K]) {
    if (!better(v, i, tv[K - 1], ti[K - 1])) return;
    tv[K - 1] = v; ti[K - 1] = i;
#pragma unroll
    for (int j = K - 1; j > 0; --j) {
        if (better(tv[j], ti[j], tv[j - 1], ti[j - 1])) {
            float fv = tv[j]; tv[j] = tv[j - 1]; tv[j - 1] = fv;
            int   fi = ti[j]; ti[j] = ti[j - 1]; ti[j - 1] = fi;
        }
    }
}

// -------- Kernel 1: scan (query norm fused, per-block top-5) -- R8 verbatim --------
__global__ void __launch_bounds__(THREADS, MIN_BLOCKS_PER_SM)
knn_scan(const float* __restrict__ q, const float* __restrict__ emb, int n) {
    __shared__ float s_q[D];
    __shared__ float s_part[WARPS_PER_BLOCK];
    __shared__ float s_norm;
    __shared__ float mv[THREADS * K];
    __shared__ int   mi[THREADS * K];

    const int t    = threadIdx.x;
    const int lane = t & 31;

    // --- normalize query into smem (per block; L2-resident after first block) ---
    {
        float v = q[t];
        float sq = v * v;
#pragma unroll
        for (int off = 16; off > 0; off >>= 1)
            sq += __shfl_down_sync(0xffffffffu, sq, off);
        if (lane == 0) s_part[t >> 5] = sq;
        __syncthreads();
        if (t == 0) {
            float tot = 0.f;
#pragma unroll
            for (int i = 0; i < WARPS_PER_BLOCK; ++i) tot += s_part[i];
            s_norm = fmaxf(sqrtf(tot), 1e-12f);
        }
        __syncthreads();
        s_q[t] = v / s_norm;
        __syncthreads();
    }

    const float4* sq4 = (const float4*)s_q;
    const float4 q0 = sq4[lane];
    const float4 q1 = sq4[lane + 32];

    float tv[K]; int ti[K];
#pragma unroll
    for (int j = 0; j < K; ++j) { tv[j] = -INFINITY; ti[j] = 0x7fffffff; }

    const int warp = (blockIdx.x * THREADS + t) >> 5;
    const int chunk = (n + TOTAL_WARPS - 1) / TOTAL_WARPS;
    int rbeg = warp * chunk;
    int rend = rbeg + chunk; if (rend > n) rend = n;
    if (rbeg > n) rbeg = n;

    const bool h16 = (lane & 16) != 0;
    const bool h8  = (lane & 8)  != 0;
    const int r_off = (h16 ? 1 : 0) + (h8 ? 2 : 0);
    const bool do_ins = (lane & 7) == 0;

    int row = rbeg;
    for (; row + 4 <= rend; row += 4) {
        float4 A[4], B[4];
#pragma unroll
        for (int r = 0; r < 4; ++r) {
            const float4* e = (const float4*)(emb + (size_t)(row + r) * D);
            A[r] = e[lane];
            B[r] = e[lane + 32];
        }
        float d[4];
#pragma unroll
        for (int r = 0; r < 4; ++r) {
            float s = fmaf(A[r].x, q0.x, fmaf(A[r].y, q0.y, fmaf(A[r].z, q0.z, A[r].w * q0.w)));
            d[r] = fmaf(B[r].x, q1.x, fmaf(B[r].y, q1.y, fmaf(B[r].z, q1.z, fmaf(B[r].w, q1.w, s))));
        }
        // 4-way warp reduce in 5 shuffles:
        float send01 = h16 ? d[0] : d[1];
        float s01 = (h16 ? d[1] : d[0]) + __shfl_xor_sync(0xffffffffu, send01, 16);
        float send23 = h16 ? d[2] : d[3];
        float s23 = (h16 ? d[3] : d[2]) + __shfl_xor_sync(0xffffffffu, send23, 16);
        float send = h8 ? s01 : s23;
        float s = (h8 ? s23 : s01) + __shfl_xor_sync(0xffffffffu, send, 8);
        s += __shfl_xor_sync(0xffffffffu, s, 4);
        s += __shfl_xor_sync(0xffffffffu, s, 2);
        s += __shfl_xor_sync(0xffffffffu, s, 1);
        // lanes 0,8,16,24 hold totals of rows row+0, row+2, row+1, row+3
        if (do_ins) insert_top5(s, row + r_off, tv, ti);
    }
    // remainder rows (<=3)
    for (; row < rend; ++row) {
        const float4* e = (const float4*)(emb + (size_t)row * D);
        float4 a = e[lane], b = e[lane + 32];
        float s = fmaf(a.x, q0.x, fmaf(a.y, q0.y, fmaf(a.z, q0.z, a.w * q0.w)));
        s = fmaf(b.x, q1.x, fmaf(b.y, q1.y, fmaf(b.z, q1.z, fmaf(b.w, q1.w, s))));
#pragma unroll
        for (int off = 16; off > 0; off >>= 1)
            s += __shfl_xor_sync(0xffffffffu, s, off);
        if (lane == 0) insert_top5(s, row, tv, ti);
    }

    // --- per-block merge of 256 per-thread lists -> block top-5 ---
#pragma unroll
    for (int j = 0; j < K; ++j) { mv[t * K + j] = tv[j]; mi[t * K + j] = ti[j]; }
    for (int sft = THREADS / 2; sft >= 1; sft >>= 1) {
        __syncthreads();
        if (t < sft) {
#pragma unroll
            for (int j = 0; j < K; ++j) { tv[j] = mv[t * K + j]; ti[j] = mi[t * K + j]; }
#pragma unroll
            for (int j = 0; j < K; ++j)
                insert_top5(mv[(t + sft) * K + j], mi[(t + sft) * K + j], tv, ti);
#pragma unroll
            for (int j = 0; j < K; ++j) { mv[t * K + j] = tv[j]; mi[t * K + j] = ti[j]; }
        }
    }
    __syncthreads();
    if (t == 0) {
#pragma unroll
        for (int j = 0; j < K; ++j) {
            g_cand_val[blockIdx.x * K + j] = mv[j];
            g_cand_idx[blockIdx.x * K + j] = mi[j];
        }
    }
}

// -------- Kernel 2: latency-optimized reduce (512 threads, batched __ldcg loads) -----
__global__ void __launch_bounds__(RED_THREADS) knn_reduce(float* __restrict__ out) {
    __shared__ float sv[RED_THREADS * K];
    __shared__ int   si[RED_THREADS * K];
    const int t = threadIdx.x;

    // Phase 1: batched independent loads (full unroll -> max MLP, one latency wall)
    float cv[PER_T]; int ci[PER_T];
#pragma unroll
    for (int u = 0; u < PER_T; ++u) {
        int c = t + u * RED_THREADS;
        bool ok = c < NCAND;
        int cc = ok ? c : 0;
        cv[u] = __ldcg(&g_cand_val[cc]);
        ci[u] = __ldcg(&g_cand_idx[cc]);
        if (!ok) { cv[u] = -INFINITY; ci[u] = 0x7fffffff; }
    }

    // Phase 2: insert into local top-5 (8 dependent inserts)
    float tv[K]; int ti[K];
#pragma unroll
    for (int j = 0; j < K; ++j) { tv[j] = -INFINITY; ti[j] = 0x7fffffff; }
#pragma unroll
    for (int u = 0; u < PER_T; ++u)
        insert_top5(cv[u], ci[u], tv, ti);

    // Phase 3: smem tree merge
#pragma unroll
    for (int j = 0; j < K; ++j) { sv[t * K + j] = tv[j]; si[t * K + j] = ti[j]; }
    for (int s = RED_THREADS / 2; s >= 1; s >>= 1) {
        __syncthreads();
        if (t < s) {
#pragma unroll
            for (int j = 0; j < K; ++j) { tv[j] = sv[t * K + j]; ti[j] = si[t * K + j]; }
#pragma unroll
            for (int j = 0; j < K; ++j)
                insert_top5(sv[(t + s) * K + j], si[(t + s) * K + j], tv, ti);
#pragma unroll
            for (int j = 0; j < K; ++j) { sv[t * K + j] = tv[j]; si[t * K + j] = ti[j]; }
        }
    }
    __syncthreads();
    if (t == 0) {
#pragma unroll
        for (int j = 0; j < K; ++j) {
            out[j]     = (float)si[j];   // top_idx (reference tuple order: idx first)
            out[K + j] = sv[j];          // top_vals
        }
    }
}

extern "C" void kernel_launch(void* const* d_in, const int* in_sizes, int n_in,
                              void* d_out, int out_size) {
    const float* q   = (const float*)d_in[0];   // [1, 256]
    const float* emb = (const float*)d_in[1];   // [N, 256]
    const int n = in_sizes[1] / D;

    knn_scan<<<BLOCKS, THREADS>>>(q, emb, n);
    knn_reduce<<<1, RED_THREADS>>>((float*)d_out);
}